// round 1
// baseline (speedup 1.0000x reference)
#include <cuda_runtime.h>

// out[i, j] = (2*x[i, j] + 3) / (i + 1), x is 8192x8192 fp32.
// Pure streaming: 512 MiB HBM traffic -> HBM-bound. float4 vectorized.

static constexpr int N_ROWS = 8192;
static constexpr int N_COLS = 8192;
static constexpr long long N_ELEMS = (long long)N_ROWS * N_COLS;   // 2^26
static constexpr int VEC = 4;
static constexpr long long N_VEC = N_ELEMS / VEC;                  // 2^24

__global__ void affine_rowdiv_kernel(const float4* __restrict__ in,
                                     float4* __restrict__ out) {
    long long idx = (long long)blockIdx.x * blockDim.x + threadIdx.x;
    if (idx >= N_VEC) return;

    // element index of first lane of this float4
    // row = (idx*4) / 8192 = idx / 2048 = idx >> 11  (all 4 elems same row: 8192 % 4 == 0)
    int row = (int)(idx >> 11);
    float inv = 1.0f / (float)(row + 1);

    float4 v = in[idx];
    float4 r;
    r.x = fmaf(2.0f, v.x, 3.0f) * inv;
    r.y = fmaf(2.0f, v.y, 3.0f) * inv;
    r.z = fmaf(2.0f, v.z, 3.0f) * inv;
    r.w = fmaf(2.0f, v.w, 3.0f) * inv;
    out[idx] = r;
}

extern "C" void kernel_launch(void* const* d_in, const int* in_sizes, int n_in,
                              void* d_out, int out_size) {
    const float4* in = (const float4*)d_in[0];
    float4* out = (float4*)d_out;

    const int threads = 256;
    const int blocks = (int)((N_VEC + threads - 1) / threads);  // 65536
    affine_rowdiv_kernel<<<blocks, threads>>>(in, out);
}

// round 2
// speedup vs baseline: 1.0226x; 1.0226x over previous
#include <cuda_runtime.h>

// out[i, j] = (2*x[i, j] + 3) / (i + 1), x is 8192x8192 fp32.
// HBM-bound streaming. R2: 8x front-batched LDG.128 per thread (MLP_eff ~8),
// streaming cache hints, 8192 CTAs (fewer wave transitions).

static constexpr int N_ROWS = 8192;
static constexpr int N_COLS = 8192;
static constexpr long long N_ELEMS = (long long)N_ROWS * N_COLS;   // 2^26
static constexpr int VEC = 4;
static constexpr long long N_VEC = N_ELEMS / VEC;                  // 2^24 float4s
static constexpr int THREADS = 256;
static constexpr int UNROLL = 8;
// 2^24 / (256*8) = 8192 blocks, exact — no tail handling needed.
static constexpr int BLOCKS = (int)(N_VEC / (THREADS * UNROLL));

__global__ void __launch_bounds__(THREADS)
affine_rowdiv_kernel(const float4* __restrict__ in, float4* __restrict__ out) {
    // Block-contiguous layout: block b owns vec range [b*2048, (b+1)*2048).
    // Iteration k covers [base + k*256, base + k*256 + 256) — fully coalesced.
    long long base = (long long)blockIdx.x * (THREADS * UNROLL) + threadIdx.x;

    // Front-batch all 8 loads -> 8 outstanding LDG.128 per thread.
    float4 v[UNROLL];
#pragma unroll
    for (int k = 0; k < UNROLL; k++) {
        v[k] = __ldcs(&in[base + (long long)k * THREADS]);
    }

#pragma unroll
    for (int k = 0; k < UNROLL; k++) {
        long long idx = base + (long long)k * THREADS;
        // row = (idx*4) >> 13 = idx >> 11  (2048 float4s per row)
        int row = (int)(idx >> 11);
        float inv = 1.0f / (float)(row + 1);
        float4 r;
        r.x = fmaf(2.0f, v[k].x, 3.0f) * inv;
        r.y = fmaf(2.0f, v[k].y, 3.0f) * inv;
        r.z = fmaf(2.0f, v[k].z, 3.0f) * inv;
        r.w = fmaf(2.0f, v[k].w, 3.0f) * inv;
        __stcs(&out[idx], r);
    }
}

extern "C" void kernel_launch(void* const* d_in, const int* in_sizes, int n_in,
                              void* d_out, int out_size) {
    const float4* in = (const float4*)d_in[0];
    float4* out = (float4*)d_out;
    affine_rowdiv_kernel<<<BLOCKS, THREADS>>>(in, out);
}